// round 10
// baseline (speedup 1.0000x reference)
#include <cuda_runtime.h>
#include <cstdint>
#include <math.h>

#define BB    32
#define DIMS  8
#define DEG   32
#define NINT  64          // intervals over [0,1]
#define P     2
#define TPB   256
#define ZBUF_BYTES 4096
#define IVSTRIDE 36       // floats per interval in smem (32 + pad), 144B

// Static scratch (no allocation allowed)
__device__ float g_fvals[BB * NINT * 4 * DIMS];        // node values, 256KB
__device__ float g_table[BB * NINT * 32];              // packed coeffs, 256KB

__device__ __forceinline__ float ex2f(float x) {
    float r; asm("ex2.approx.f32 %0, %1;" : "=f"(r) : "f"(x)); return r;
}
__device__ __forceinline__ unsigned long long pack2(float lo, float hi) {
    unsigned long long r;
    asm("mov.b64 %0, {%1, %2};" : "=l"(r) : "f"(lo), "f"(hi)); return r;
}
__device__ __forceinline__ unsigned long long fma2(unsigned long long a,
                                                   unsigned long long b,
                                                   unsigned long long c) {
    unsigned long long r;
    asm("fma.rn.f32x2 %0, %1, %2, %3;" : "=l"(r) : "l"(a), "l"(b), "l"(c));
    return r;
}
__device__ __forceinline__ uint32_t smem_u32(const void* p) {
    uint32_t a;
    asm("{ .reg .u64 t; cvta.to.shared.u64 t, %1; cvt.u32.u64 %0, t; }"
        : "=r"(a) : "l"(p));
    return a;
}

// Kernel A: exact basis-mixture values at the 4 Lagrange nodes of each interval.
// thread id = (b*NINT + i)*4 + k ;  x = (i + k/3)/NINT
__global__ void build_fvals(const float* __restrict__ weights) {
    int t = blockIdx.x * blockDim.x + threadIdx.x;
    if (t >= BB * NINT * 4) return;
    const int k = t & 3;
    const int bi = t >> 2;
    const int i = bi & (NINT - 1);
    const int b = bi >> 6;

    const float x = ((float)i + (float)k * (1.0f / 3.0f)) * (1.0f / NINT);
    const float s = 1.01f / 31.0f;

    float phi[DEG];
#pragma unroll
    for (int g = 0; g < DEG; g++) {
        const float d = x - (float)g * s;
        phi[g] = expf(-12.5f * d * d);
    }
    const float* w = weights + b * DIMS * DEG;
    float* fo = g_fvals + ((size_t)bi * 4 + k) * DIMS;
#pragma unroll
    for (int d = 0; d < DIMS; d++) {
        float acc = 0.0f;
#pragma unroll
        for (int g = 0; g < DEG; g++)
            acc = fmaf(phi[g], w[d * DEG + g], acc);
        fo[d] = acc;
    }
}

// Kernel B: monomial coeffs from the 4 node values (Lagrange, nodes u=0,1/3,2/3,1)
// thread id = (b*NINT + i)*DIMS + d
__global__ void build_coeffs() {
    int t = blockIdx.x * blockDim.x + threadIdx.x;
    if (t >= BB * NINT * DIMS) return;
    const int d = t & 7;
    const int bi = t >> 3;

    const float* fv = g_fvals + (size_t)bi * 4 * DIMS;
    const float f0 = fv[0 * DIMS + d], f1 = fv[1 * DIMS + d];
    const float f2 = fv[2 * DIMS + d], f3 = fv[3 * DIMS + d];

    const float c0 = f0;
    const float c1 = 0.5f * (-11.0f * f0 + 18.0f * f1 - 9.0f * f2 + 2.0f * f3);
    const float c2 = 0.5f * ( 18.0f * f0 - 45.0f * f1 + 36.0f * f2 - 9.0f * f3);
    const float c3 = 0.5f * ( -9.0f * f0 + 27.0f * f1 - 27.0f * f2 + 9.0f * f3);

    // packed layout per (b,i): 32 floats = [dp][c][half], dp = d>>1, half = d&1
    float* tb = g_table + (size_t)bi * 32 + (d >> 1) * 8 + (d & 1);
    tb[0] = c0; tb[2] = c1; tb[4] = c2; tb[6] = c3;
}

__global__ __launch_bounds__(TPB) void basis_eval(
    const float* __restrict__ positions,  // (B, N)
    float* __restrict__ out,              // (B, N, DIMS) [+ zeros half]
    int N, int write_zeros)
{
    __shared__ __align__(16) float stab[NINT * IVSTRIDE];   // 9216B padded table
    __shared__ __align__(16) float zbuf[ZBUF_BYTES / 4];    // stays zero

    const int b    = blockIdx.y;
    const int tid  = threadIdx.x;
    const int lane = tid & 31;
    const int wrp  = tid >> 5;

    const int nblk  = blockIdx.x * (TPB * P);     // 512 positions / block
    const int nwarp = nblk + wrp * (32 * P);
    const float* pp = positions + (size_t)b * N + nwarp;
    const size_t basew = ((size_t)b * N + nwarp) * DIMS;

    // zero staging buffer
    {
        const float4 z = {0.0f, 0.0f, 0.0f, 0.0f};
        reinterpret_cast<float4*>(zbuf)[tid] = z;
    }
    // load this batch's table slice (2048 floats) into padded smem
    {
        const float* src = g_table + (size_t)b * NINT * 32;
#pragma unroll
        for (int v = 0; v < 2; v++) {
            const int j = tid * 8 + v * 4;            // 8 floats/thread
            const float4 val = *reinterpret_cast<const float4*>(src + j);
            const int iv = j >> 5, off = j & 31;
            *reinterpret_cast<float4*>(stab + iv * IVSTRIDE + off) = val;
        }
    }
    __syncthreads();

    // zeros half via bulk async stores (16KB block span), overlapped with eval
    if (write_zeros && tid == 0) {
        asm volatile("fence.proxy.async.shared::cta;" ::: "memory");
        const size_t R = (size_t)gridDim.y * (size_t)N * DIMS;
        float* zdst = out + R + ((size_t)b * N + nblk) * DIMS;
        const uint32_t src = smem_u32(zbuf);
#pragma unroll
        for (int i = 0; i < 4; i++) {
            asm volatile(
                "cp.async.bulk.global.shared::cta.bulk_group [%0], [%1], %2;"
                :: "l"(zdst + i * (ZBUF_BYTES / 4)), "r"(src), "n"(ZBUF_BYTES)
                : "memory");
        }
        asm volatile("cp.async.bulk.commit_group;" ::: "memory");
    }

#pragma unroll
    for (int p = 0; p < P; p++) {
        const float x = pp[lane + 32 * p];

        float t = x * (float)NINT;
        float fi = floorf(t);
        int i = (int)fi;
        i = (i < 0) ? 0 : ((i > NINT - 1) ? NINT - 1 : i);
        const float u = t - (float)i;
        const unsigned long long u2 = pack2(u, u);

        const float* ivp = stab + i * IVSTRIDE;
        unsigned long long r[4];
#pragma unroll
        for (int dp = 0; dp < 4; dp++) {
            // [c0pair, c1pair] and [c2pair, c3pair] as two LDS.128
            const ulonglong2 lo = *reinterpret_cast<const ulonglong2*>(ivp + dp * 8);
            const ulonglong2 hi = *reinterpret_cast<const ulonglong2*>(ivp + dp * 8 + 4);
            unsigned long long h = fma2(hi.y, u2, hi.x);   // c3*u + c2
            h = fma2(h, u2, lo.y);                          // *u + c1
            r[dp] = fma2(h, u2, lo.x);                      // *u + c0
        }

        float* o = out + basew + (size_t)(32 * p + lane) * DIMS;
        ulonglong2 v0; v0.x = r[0]; v0.y = r[1];
        ulonglong2 v1; v1.x = r[2]; v1.y = r[3];
        *reinterpret_cast<ulonglong2*>(o)     = v0;
        *reinterpret_cast<ulonglong2*>(o + 4) = v1;
    }

    if (write_zeros && tid == 0) {
        asm volatile("cp.async.bulk.wait_group 0;" ::: "memory");
    }
}

extern "C" void kernel_launch(void* const* d_in, const int* in_sizes, int n_in,
                              void* d_out, int out_size)
{
    const float* weights   = (const float*)d_in[0];
    const float* positions = (const float*)d_in[2];
    float* out = (float*)d_out;

    const int N = in_sizes[2] / BB;                 // 65536
    const long long R = (long long)BB * N * DIMS;
    const int write_zeros = (out_size >= 2 * R) ? 1 : 0;

    build_fvals<<<(BB * NINT * 4 + 255) / 256, 256>>>(weights);
    build_coeffs<<<(BB * NINT * DIMS + 255) / 256, 256>>>();

    dim3 grid(N / (TPB * P), BB);                   // (128, 32)
    basis_eval<<<grid, TPB>>>(positions, out, N, write_zeros);
}

// round 11
// speedup vs baseline: 1.2778x; 1.2778x over previous
#include <cuda_runtime.h>
#include <cstdint>

#define BB    32
#define DIMS  8
#define DEG   32
#define S     2       // position-pair layers per thread (64 positions/warp)
#define TPB   256
#define ZBUF_BYTES 4096

__device__ __forceinline__ float ex2f(float x) {
    float r; asm("ex2.approx.f32 %0, %1;" : "=f"(r) : "f"(x)); return r;
}
__device__ __forceinline__ unsigned long long pack2(float lo, float hi) {
    unsigned long long r;
    asm("mov.b64 %0, {%1, %2};" : "=l"(r) : "f"(lo), "f"(hi)); return r;
}
__device__ __forceinline__ void unpack2(unsigned long long v, float& lo, float& hi) {
    asm("mov.b64 {%0, %1}, %2;" : "=f"(lo), "=f"(hi) : "l"(v));
}
__device__ __forceinline__ unsigned long long fma2(unsigned long long a,
                                                   unsigned long long b,
                                                   unsigned long long c) {
    unsigned long long r;
    asm("fma.rn.f32x2 %0, %1, %2, %3;" : "=l"(r) : "l"(a), "l"(b), "l"(c));
    return r;
}
__device__ __forceinline__ unsigned long long mul2(unsigned long long a,
                                                   unsigned long long b) {
    unsigned long long r;
    asm("mul.rn.f32x2 %0, %1, %2;" : "=l"(r) : "l"(a), "l"(b));
    return r;
}
__device__ __forceinline__ uint32_t smem_u32(const void* p) {
    uint32_t a;
    asm("{ .reg .u64 t; cvta.to.shared.u64 t, %1; cvt.u32.u64 %0, t; }"
        : "=r"(a) : "l"(p));
    return a;
}

__global__ __launch_bounds__(TPB, 5) void basis_kernel(
    const float* __restrict__ weights,    // (B, DIMS, DEG)
    const float* __restrict__ positions,  // (B, N)
    float* __restrict__ out,              // (B, N, DIMS) [+ zeros half]
    int N, int write_zeros)
{
    // swd[g*8 + d] = (w'[d][g], w'[d][g])  duplicated pairs, w' = w * c_g
    __shared__ __align__(16) unsigned long long swd[DEG * DIMS];   // 2KB
    __shared__ __align__(16) float zbuf[ZBUF_BYTES / 4];           // stays zero

    const int b    = blockIdx.y;
    const int tid  = threadIdx.x;
    const int lane = tid & 31;
    const int wrp  = tid >> 5;
    const int h    = lane & 1;        // dim half: 0 -> dims 0-3, 1 -> dims 4-7
    const int k    = lane >> 1;       // position index within half-layer (0..15)

    const int nblk  = blockIdx.x * (TPB * 2);     // 512 positions / block
    const int nwarp = nblk + wrp * 64;            // 64 / warp
    const float* pp = positions + (size_t)b * N + nwarp;
    float* owarp = out + ((size_t)b * N + nwarp) * DIMS;

    const float s = 1.01f / 31.0f;
    const float L = 12.5f * 1.4426950408889634f;

    // zero staging buffer (1 STS.128/thread)
    {
        const float4 z = {0.0f, 0.0f, 0.0f, 0.0f};
        reinterpret_cast<float4*>(zbuf)[tid] = z;
    }
    // build duplicated weight table: tid = g*8 + d, fold c_g = 2^(-L s^2 g^2)
    {
        const int g = tid >> 3;
        const int d = tid & 7;
        const float wv = weights[b * DIMS * DEG + d * DEG + g] *
                         ex2f(-L * s * s * (float)(g * g));
        swd[tid] = pack2(wv, wv);
    }
    __syncthreads();

    // zeros half via bulk async stores (16KB block span), overlapped with compute
    if (write_zeros && tid == 0) {
        asm volatile("fence.proxy.async.shared::cta;" ::: "memory");
        const size_t R = (size_t)gridDim.y * (size_t)N * DIMS;
        float* zdst = out + R + ((size_t)b * N + nblk) * DIMS;
        const uint32_t src = smem_u32(zbuf);
#pragma unroll
        for (int i = 0; i < 4; i++) {
            asm volatile(
                "cp.async.bulk.global.shared::cta.bulk_group [%0], [%1], %2;"
                :: "l"(zdst + i * (ZBUF_BYTES / 4)), "r"(src), "n"(ZBUF_BYTES)
                : "memory");
        }
        asm volatile("cp.async.bulk.commit_group;" ::: "memory");
    }

    // Layer sl: pair positions pA = sl*32 + k, pB = sl*32 + 16 + k.
    // Recurrence state packed over (pA, pB): e_g = e0 * q^g (c_g folded in w).
    unsigned long long eD[S], qD[S];
#pragma unroll
    for (int sl = 0; sl < S; sl++) {
        const float xA = pp[sl * 32 + k];
        const float xB = pp[sl * 32 + 16 + k];
        eD[sl] = pack2(ex2f(-L * xA * xA), ex2f(-L * xB * xB));
        qD[sl] = pack2(ex2f(2.0f * L * s * xA), ex2f(2.0f * L * s * xB));
    }

    // acc[sl][j] = (res_pA_{4h+j}, res_pB_{4h+j})
    unsigned long long acc[S][4];
#pragma unroll
    for (int sl = 0; sl < S; sl++)
#pragma unroll
        for (int j = 0; j < 4; j++)
            acc[sl][j] = 0ull;

    const ulonglong2* wp = reinterpret_cast<const ulonglong2*>(swd + 4 * h);

#pragma unroll
    for (int g = 0; g < DEG; g++) {
        const ulonglong2 w01 = wp[g * 4];       // dims 4h, 4h+1 (duplicated)
        const ulonglong2 w23 = wp[g * 4 + 1];   // dims 4h+2, 4h+3
#pragma unroll
        for (int sl = 0; sl < S; sl++) {
            acc[sl][0] = fma2(eD[sl], w01.x, acc[sl][0]);
            acc[sl][1] = fma2(eD[sl], w01.y, acc[sl][1]);
            acc[sl][2] = fma2(eD[sl], w23.x, acc[sl][2]);
            acc[sl][3] = fma2(eD[sl], w23.y, acc[sl][3]);
            eD[sl] = mul2(eD[sl], qD[sl]);
        }
    }

    // Contiguous stores: per layer, pA block and pB block are each 512B/warp.
#pragma unroll
    for (int sl = 0; sl < S; sl++) {
        float lo0, hi0, lo1, hi1, lo2, hi2, lo3, hi3;
        unpack2(acc[sl][0], lo0, hi0);
        unpack2(acc[sl][1], lo1, hi1);
        unpack2(acc[sl][2], lo2, hi2);
        unpack2(acc[sl][3], lo3, hi3);
        float4 vA = {lo0, lo1, lo2, lo3};
        float4 vB = {hi0, hi1, hi2, hi3};
        // lane 2k+h -> pA at (sl*32+k)*8 + h*4 : contiguous 512B across warp
        *reinterpret_cast<float4*>(owarp + (sl * 32 + k) * 8 + h * 4)      = vA;
        *reinterpret_cast<float4*>(owarp + (sl * 32 + 16 + k) * 8 + h * 4) = vB;
    }

    if (write_zeros && tid == 0) {
        asm volatile("cp.async.bulk.wait_group 0;" ::: "memory");
    }
}

extern "C" void kernel_launch(void* const* d_in, const int* in_sizes, int n_in,
                              void* d_out, int out_size)
{
    const float* weights   = (const float*)d_in[0];
    const float* positions = (const float*)d_in[2];
    float* out = (float*)d_out;

    const int N = in_sizes[2] / BB;                 // 65536
    const long long R = (long long)BB * N * DIMS;
    const int write_zeros = (out_size >= 2 * R) ? 1 : 0;

    dim3 grid(N / (TPB * 2), BB);                   // (128, 32)
    basis_kernel<<<grid, TPB>>>(weights, positions, out, N, write_zeros);
}

// round 13
// speedup vs baseline: 1.4389x; 1.1261x over previous
#include <cuda_runtime.h>
#include <cstdint>

#define BB    32
#define DIMS  8
#define DEG   32
#define P     2
#define TPB   256
#define ZBUF_BYTES 4096

__device__ __forceinline__ float ex2f(float x) {
    float r; asm("ex2.approx.f32 %0, %1;" : "=f"(r) : "f"(x)); return r;
}
__device__ __forceinline__ unsigned long long pack2(float lo, float hi) {
    unsigned long long r;
    asm("mov.b64 %0, {%1, %2};" : "=l"(r) : "f"(lo), "f"(hi)); return r;
}
__device__ __forceinline__ void unpack2(unsigned long long v, float& lo, float& hi) {
    asm("mov.b64 {%0, %1}, %2;" : "=f"(lo), "=f"(hi) : "l"(v));
}
__device__ __forceinline__ unsigned long long fma2(unsigned long long a,
                                                   unsigned long long b,
                                                   unsigned long long c) {
    unsigned long long r;
    asm("fma.rn.f32x2 %0, %1, %2, %3;" : "=l"(r) : "l"(a), "l"(b), "l"(c));
    return r;
}
__device__ __forceinline__ unsigned long long mul2(unsigned long long a,
                                                   unsigned long long b) {
    unsigned long long r;
    asm("mul.rn.f32x2 %0, %1, %2;" : "=l"(r) : "l"(a), "l"(b));
    return r;
}
__device__ __forceinline__ uint32_t smem_u32(const void* p) {
    uint32_t a;
    asm("{ .reg .u64 t; cvta.to.shared.u64 t, %1; cvt.u32.u64 %0, t; }"
        : "=r"(a) : "l"(p));
    return a;
}
// 256-bit dense store: 8 fp32 = 32B per lane, warp = 1KB contiguous.
// Pointer is 32B-aligned by construction (basew and lane offsets are
// multiples of 8 floats).
__device__ __forceinline__ void stg256(float* p,
                                       unsigned long long a0, unsigned long long a1,
                                       unsigned long long a2, unsigned long long a3) {
    float f0, f1, f2, f3, f4, f5, f6, f7;
    unpack2(a0, f0, f1); unpack2(a1, f2, f3);
    unpack2(a2, f4, f5); unpack2(a3, f6, f7);
    asm volatile("st.global.v8.f32 [%0], {%1,%2,%3,%4,%5,%6,%7,%8};"
                 :: "l"(p), "f"(f0), "f"(f1), "f"(f2), "f"(f3),
                    "f"(f4), "f"(f5), "f"(f6), "f"(f7)
                 : "memory");
}

__global__ __launch_bounds__(TPB, 5) void basis_kernel(
    const float* __restrict__ weights,    // (B, DIMS, DEG)
    const float* __restrict__ positions,  // (B, N)
    float* __restrict__ out,              // (B, N, DIMS) [+ zeros half]
    int N, int write_zeros)
{
    // sw2[g*4 + dp] = (w'[2dp][g], w'[2dp+1][g]) with w' = w * c_g pre-folded
    __shared__ __align__(16) unsigned long long sw2[DEG * 4];
    __shared__ __align__(16) float zbuf[ZBUF_BYTES / 4];   // stays zero

    const int b    = blockIdx.y;
    const int tid  = threadIdx.x;
    const int lane = tid & 31;
    const int wrp  = tid >> 5;

    const int nblk  = blockIdx.x * (TPB * P);     // 512 positions per block
    const int nwarp = nblk + wrp * (32 * P);      // 64 per warp
    const float* pp = positions + (size_t)b * N + nwarp;
    const size_t basew = ((size_t)b * N + nwarp) * DIMS;

    const float s = 1.01f / 31.0f;
    const float L = 12.5f * 1.4426950408889634f;

    // Zero the smem staging buffer (1 STS.128/thread)
    {
        const float4 z = {0.0f, 0.0f, 0.0f, 0.0f};
        reinterpret_cast<float4*>(zbuf)[tid] = z;
    }
    {
        // float view index = g*8 + d == tid; fold c_g = 2^(-L s^2 g^2) into w
        const int g = tid >> 3;
        const int d = tid & 7;
        const float cg = ex2f(-L * s * s * (float)(g * g));
        reinterpret_cast<float*>(sw2)[tid] = weights[b * DIMS * DEG + d * DEG + g] * cg;
    }
    __syncthreads();

    // Zeros half via bulk async stores (16KB block span), overlapped with compute
    if (write_zeros && tid == 0) {
        asm volatile("fence.proxy.async.shared::cta;" ::: "memory");
        const size_t R = (size_t)gridDim.y * (size_t)N * DIMS;
        float* zdst = out + R + ((size_t)b * N + nblk) * DIMS;
        const uint32_t src = smem_u32(zbuf);
#pragma unroll
        for (int i = 0; i < 4; i++) {
            asm volatile(
                "cp.async.bulk.global.shared::cta.bulk_group [%0], [%1], %2;"
                :: "l"(zdst + i * (ZBUF_BYTES / 4)), "r"(src), "n"(ZBUF_BYTES)
                : "memory");
        }
        asm volatile("cp.async.bulk.commit_group;" ::: "memory");
    }

    // Coalesced position loads (stride-32 interleave within the warp's 64)
    float x[P];
#pragma unroll
    for (int p = 0; p < P; p++)
        x[p] = pp[lane + 32 * p];

    // e_g = e_0 * q^g * c_g :  e_0 = 2^(-L x^2),  q = 2^(2 L s x)
    unsigned long long eD[P], qD[P];
#pragma unroll
    for (int p = 0; p < P; p++) {
        const float e0 = ex2f(-L * x[p] * x[p]);
        const float q  = ex2f(2.0f * L * s * x[p]);
        eD[p] = pack2(e0, e0);
        qD[p] = pack2(q, q);
    }

    unsigned long long acc[P][4];
#pragma unroll
    for (int p = 0; p < P; p++)
#pragma unroll
        for (int dp = 0; dp < 4; dp++)
            acc[p][dp] = 0ull;

#pragma unroll
    for (int g = 0; g < DEG; g++) {
        const ulonglong2 w01 = *reinterpret_cast<const ulonglong2*>(sw2 + g * 4);
        const ulonglong2 w23 = *reinterpret_cast<const ulonglong2*>(sw2 + g * 4 + 2);
#pragma unroll
        for (int p = 0; p < P; p++) {
            acc[p][0] = fma2(eD[p], w01.x, acc[p][0]);
            acc[p][1] = fma2(eD[p], w01.y, acc[p][1]);
            acc[p][2] = fma2(eD[p], w23.x, acc[p][2]);
            acc[p][3] = fma2(eD[p], w23.y, acc[p][3]);
            eD[p] = mul2(eD[p], qD[p]);
        }
    }

    // Dense 256-bit stores: warp writes 1KB contiguous per instruction
#pragma unroll
    for (int p = 0; p < P; p++) {
        float* o = out + basew + (size_t)(32 * p + lane) * DIMS;
        stg256(o, acc[p][0], acc[p][1], acc[p][2], acc[p][3]);
    }

    if (write_zeros && tid == 0) {
        asm volatile("cp.async.bulk.wait_group 0;" ::: "memory");
    }
}

extern "C" void kernel_launch(void* const* d_in, const int* in_sizes, int n_in,
                              void* d_out, int out_size)
{
    const float* weights   = (const float*)d_in[0];
    const float* positions = (const float*)d_in[2];
    float* out = (float*)d_out;

    const int N = in_sizes[2] / BB;                 // 65536
    const long long R = (long long)BB * N * DIMS;
    const int write_zeros = (out_size >= 2 * R) ? 1 : 0;

    dim3 grid(N / (TPB * P), BB);                   // (128, 32)
    basis_kernel<<<grid, TPB>>>(weights, positions, out, N, write_zeros);
}